// round 11
// baseline (speedup 1.0000x reference)
#include <cuda_runtime.h>
#include <cuda_fp16.h>
#include <cuda_bf16.h>
#include <math.h>

#define N_ 32
#define C_ 512
#define P_ 1024
#define K_ 64
#define ALPHAF 100.0f
#define EPSF 1e-12f
#define MSCALE 2048.0f
#define INV_MSCALE 4.8828125e-4f

typedef unsigned int u32;
typedef unsigned short u16;

// ---------------- scratch (no init required) ---------------------------------
__device__ float g_asum16[N_ * 16 * K_];      // per-(n, p-tile) asum slices
__device__ float g_rss8[N_ * 8 * K_];         // per-(n, c-tile) row-sumsq slices
__device__ u16 g_abf[(size_t)N_ * K_ * P_];   // bf16 of a*invn

// ---------------- helpers ----------------------------------------------------
__device__ __forceinline__ u32 smem_u32(const void* p) {
    u32 a;
    asm("{ .reg .u64 t; cvta.to.shared.u64 t, %1; cvt.u32.u64 %0, t; }" : "=r"(a) : "l"(p));
    return a;
}
__device__ __forceinline__ void ldsm4(u32* r, u32 addr) {
    asm volatile("ldmatrix.sync.aligned.m8n8.x4.shared.b16 {%0,%1,%2,%3}, [%4];"
                 : "=r"(r[0]), "=r"(r[1]), "=r"(r[2]), "=r"(r[3]) : "r"(addr));
}
__device__ __forceinline__ void ldsm4t(u32* r, u32 addr) {
    asm volatile("ldmatrix.sync.aligned.m8n8.x4.trans.shared.b16 {%0,%1,%2,%3}, [%4];"
                 : "=r"(r[0]), "=r"(r[1]), "=r"(r[2]), "=r"(r[3]) : "r"(addr));
}
__device__ __forceinline__ void mma16816(float* d, const u32* a, const u32* b) {
    asm volatile(
        "mma.sync.aligned.m16n8k16.row.col.f32.f16.f16.f32 "
        "{%0,%1,%2,%3}, {%4,%5,%6,%7}, {%8,%9}, {%0,%1,%2,%3};"
        : "+f"(d[0]), "+f"(d[1]), "+f"(d[2]), "+f"(d[3])
        : "r"(a[0]), "r"(a[1]), "r"(a[2]), "r"(a[3]), "r"(b[0]), "r"(b[1]));
}
__device__ __forceinline__ void mma16816bf(float* d, const u32* a, const u32* b) {
    asm volatile(
        "mma.sync.aligned.m16n8k16.row.col.f32.bf16.bf16.f32 "
        "{%0,%1,%2,%3}, {%4,%5,%6,%7}, {%8,%9}, {%0,%1,%2,%3};"
        : "+f"(d[0]), "+f"(d[1]), "+f"(d[2]), "+f"(d[3])
        : "r"(a[0]), "r"(a[1]), "r"(a[2]), "r"(a[3]), "r"(b[0]), "r"(b[1]));
}
__device__ __forceinline__ void split2(float v, u32& hbits, u32& mbits) {
    __half h = __float2half_rn(v);
    __half m = __float2half_rn((v - __half2float(h)) * MSCALE);
    hbits = (u32)__half_as_ushort(h);
    mbits = (u32)__half_as_ushort(m);
}

// ---------------------------------------------------------------------------
// K1: logits D[k=64, p=64] = sum_c (2a*w)[k,c]*x[c,p]. On-the-fly fp16
// 2-plane split; invn + bias computed in-block; asum per-block slice.
// grid (16,32), 128 thr. smem 32KB: WH 8K | WM 8K | XH 8K | XM 8K.
// Each warp owns 64k x 16p.
// ---------------------------------------------------------------------------
__global__ __launch_bounds__(128) void k1_assign(const float* __restrict__ x,
                                                 const float* __restrict__ vocabs) {
    __shared__ __align__(16) char sm[32768];
    u32 sb = smem_u32(sm);
    const u32 WH = sb, WM = sb + 8192, XH = sb + 16384, XM = sb + 24576;
    float* ssacc = (float*)sm;            // [0,64)    post-mainloop
    float* sbias = (float*)sm + 64;       // [64,128)
    float* sasum = (float*)sm + 128;      // [128,384)

    int t = threadIdx.x;
    int warp = t >> 5, lane = t & 31;
    int g = lane >> 2, t4 = lane & 3;
    int jA = lane >> 3, rA = lane & 7;
    int n = blockIdx.y, p0 = blockIdx.x * 64;
    int pw = warp * 16;

    float dh[4][2][4], dl[4][2][4];
#pragma unroll
    for (int a = 0; a < 4; a++)
#pragma unroll
        for (int b = 0; b < 2; b++)
#pragma unroll
            for (int q = 0; q < 4; q++) { dh[a][b][q] = 0.0f; dl[a][b][q] = 0.0f; }

    const float* xb = x + (size_t)n * C_ * P_ + p0;
    int px = 2 * (t & 31);      // p-pair this thread stages (0..62)
    int cpar = t >> 5;          // c parity 0..3
    int nbx = px >> 3;
    float ssx = 0.0f, ssy = 0.0f;
    float wacc[16];
#pragma unroll
    for (int i = 0; i < 16; i++) wacc[i] = 0.0f;

    for (int ch = 0; ch < 8; ch++) {
        int c0 = ch * 64;
        __syncthreads();
        // stage w (64k x 64c), accumulate raw sumsq for bias
        {
            int cp = lane;
            int c = 2 * cp, cb = c >> 3;
#pragma unroll
            for (int i = 0; i < 16; i++) {
                int k = warp + 4 * i;
                float2 v = *(const float2*)(vocabs + k * C_ + c0 + c);
                wacc[i] = fmaf(v.x, v.x, fmaf(v.y, v.y, wacc[i]));
                v.x *= 2.0f * ALPHAF; v.y *= 2.0f * ALPHAF;
                u32 hx, mx_, hy, my_;
                split2(v.x, hx, mx_);
                split2(v.y, hy, my_);
                u32 addr = (u32)(k * 128) + (((u32)cb ^ (u32)(k & 7)) << 4) + (c & 7) * 2;
                *(u32*)(sm + addr) = hx | (hy << 16);
                *(u32*)(sm + 8192 + addr) = mx_ | (my_ << 16);
            }
        }
        // stage x (64c x 64p), accumulate per-p sumsq
#pragma unroll
        for (int i = 0; i < 16; i++) {
            int cc = cpar + 4 * i;
            float2 v = *(const float2*)(xb + (size_t)(c0 + cc) * P_ + px);
            ssx = fmaf(v.x, v.x, ssx);
            ssy = fmaf(v.y, v.y, ssy);
            u32 hx, mx_, hy, my_;
            split2(v.x, hx, mx_);
            split2(v.y, hy, my_);
            u32 off = (u32)(cc * 128) + (((u32)nbx ^ (u32)(cc & 7)) << 4) + (px & 7) * 2;
            *(u32*)(sm + 16384 + off) = hx | (hy << 16);
            *(u32*)(sm + 24576 + off) = mx_ | (my_ << 16);
        }
        __syncthreads();

#pragma unroll
        for (int ks = 0; ks < 4; ks++) {
            u32 Ah[4][4], Am[4][4], Bh[4], Bm[4];
#pragma unroll
            for (int mi = 0; mi < 4; mi++) {
                int k = mi * 16 + ((jA & 1) << 3) + rA;
                int cb = ks * 2 + (jA >> 1);
                u32 addr = (u32)(k * 128) + (((u32)cb ^ (u32)(k & 7)) << 4);
                ldsm4(Ah[mi], WH + addr);
                ldsm4(Am[mi], WM + addr);
            }
            {
                int c = ks * 16 + ((jA & 1) << 3) + rA;
                int nb = warp * 2 + (jA >> 1);
                u32 off = (u32)(c * 128) + (((u32)nb ^ (u32)(c & 7)) << 4);
                ldsm4t(Bh, XH + off);
                ldsm4t(Bm, XM + off);
            }
#pragma unroll
            for (int mi = 0; mi < 4; mi++)
#pragma unroll
                for (int nh = 0; nh < 2; nh++) {
                    mma16816(dh[mi][nh], Ah[mi], &Bh[nh * 2]);
                    mma16816(dl[mi][nh], Ah[mi], &Bm[nh * 2]);
                    mma16816(dl[mi][nh], Am[mi], &Bh[nh * 2]);
                }
        }
    }

    // ---- post-mainloop reductions into reused smem ----
    __syncthreads();
    if (t < 64) ssacc[t] = 0.0f;
    __syncthreads();
    atomicAdd(&ssacc[px], ssx);
    atomicAdd(&ssacc[px + 1], ssy);
#pragma unroll
    for (int i = 0; i < 16; i++) {
        float s = wacc[i];
#pragma unroll
        for (int o = 16; o; o >>= 1) s += __shfl_xor_sync(0xffffffffu, s, o);
        if (lane == 0) sbias[warp + 4 * i] = -ALPHAF * sqrtf(s);
    }
    __syncthreads();

    float d[4][2][4];
#pragma unroll
    for (int mi = 0; mi < 4; mi++)
#pragma unroll
        for (int nj = 0; nj < 2; nj++)
#pragma unroll
            for (int q = 0; q < 4; q++)
                d[mi][nj][q] = fmaf(dl[mi][nj][q], INV_MSCALE, dh[mi][nj][q]);

    float invp[2][2], bias[4][2];
#pragma unroll
    for (int nj = 0; nj < 2; nj++) {
        int pl = pw + nj * 8 + 2 * t4;
        invp[nj][0] = 1.0f / fmaxf(sqrtf(ssacc[pl]), EPSF);
        invp[nj][1] = 1.0f / fmaxf(sqrtf(ssacc[pl + 1]), EPSF);
    }
#pragma unroll
    for (int mi = 0; mi < 4; mi++) {
        bias[mi][0] = sbias[mi * 16 + g];
        bias[mi][1] = sbias[mi * 16 + g + 8];
    }
    float lg[4][2][4];
    float mx[2][2];
#pragma unroll
    for (int nj = 0; nj < 2; nj++) { mx[nj][0] = -1e30f; mx[nj][1] = -1e30f; }
#pragma unroll
    for (int mi = 0; mi < 4; mi++)
#pragma unroll
        for (int nj = 0; nj < 2; nj++) {
            lg[mi][nj][0] = fmaf(d[mi][nj][0], invp[nj][0], bias[mi][0]);
            lg[mi][nj][1] = fmaf(d[mi][nj][1], invp[nj][1], bias[mi][0]);
            lg[mi][nj][2] = fmaf(d[mi][nj][2], invp[nj][0], bias[mi][1]);
            lg[mi][nj][3] = fmaf(d[mi][nj][3], invp[nj][1], bias[mi][1]);
            mx[nj][0] = fmaxf(mx[nj][0], fmaxf(lg[mi][nj][0], lg[mi][nj][2]));
            mx[nj][1] = fmaxf(mx[nj][1], fmaxf(lg[mi][nj][1], lg[mi][nj][3]));
        }
#pragma unroll
    for (int nj = 0; nj < 2; nj++)
#pragma unroll
        for (int cc = 0; cc < 2; cc++) {
            float m = mx[nj][cc];
#pragma unroll
            for (int o = 4; o <= 16; o <<= 1) m = fmaxf(m, __shfl_xor_sync(0xffffffffu, m, o));
            mx[nj][cc] = m;
        }
    float sx[2][2];
#pragma unroll
    for (int nj = 0; nj < 2; nj++) { sx[nj][0] = 0.0f; sx[nj][1] = 0.0f; }
#pragma unroll
    for (int mi = 0; mi < 4; mi++)
#pragma unroll
        for (int nj = 0; nj < 2; nj++) {
            lg[mi][nj][0] = __expf(lg[mi][nj][0] - mx[nj][0]);
            lg[mi][nj][1] = __expf(lg[mi][nj][1] - mx[nj][1]);
            lg[mi][nj][2] = __expf(lg[mi][nj][2] - mx[nj][0]);
            lg[mi][nj][3] = __expf(lg[mi][nj][3] - mx[nj][1]);
            sx[nj][0] += lg[mi][nj][0] + lg[mi][nj][2];
            sx[nj][1] += lg[mi][nj][1] + lg[mi][nj][3];
        }
#pragma unroll
    for (int nj = 0; nj < 2; nj++)
#pragma unroll
        for (int cc = 0; cc < 2; cc++) {
            float s = sx[nj][cc];
#pragma unroll
            for (int o = 4; o <= 16; o <<= 1) s += __shfl_xor_sync(0xffffffffu, s, o);
            sx[nj][cc] = 1.0f / s;
        }
    float asl[4][2];
#pragma unroll
    for (int mi = 0; mi < 4; mi++) { asl[mi][0] = 0.0f; asl[mi][1] = 0.0f; }
    u16* ab = g_abf + (size_t)n * K_ * P_;
#pragma unroll
    for (int mi = 0; mi < 4; mi++)
#pragma unroll
        for (int nj = 0; nj < 2; nj++) {
            int p = p0 + pw + nj * 8 + 2 * t4;
            int k0_ = mi * 16 + g;
            float a00 = lg[mi][nj][0] * sx[nj][0];
            float a01 = lg[mi][nj][1] * sx[nj][1];
            float a10 = lg[mi][nj][2] * sx[nj][0];
            float a11 = lg[mi][nj][3] * sx[nj][1];
            asl[mi][0] += a00 + a01;
            asl[mi][1] += a10 + a11;
            u32 w0 = (u32)__bfloat16_as_ushort(__float2bfloat16(a00 * invp[nj][0])) |
                     ((u32)__bfloat16_as_ushort(__float2bfloat16(a01 * invp[nj][1])) << 16);
            u32 w1 = (u32)__bfloat16_as_ushort(__float2bfloat16(a10 * invp[nj][0])) |
                     ((u32)__bfloat16_as_ushort(__float2bfloat16(a11 * invp[nj][1])) << 16);
            *(u32*)(ab + (size_t)k0_ * P_ + p) = w0;
            *(u32*)(ab + (size_t)(k0_ + 8) * P_ + p) = w1;
        }
#pragma unroll
    for (int mi = 0; mi < 4; mi++)
#pragma unroll
        for (int h = 0; h < 2; h++) {
            float s = asl[mi][h];
            s += __shfl_xor_sync(0xffffffffu, s, 1);
            s += __shfl_xor_sync(0xffffffffu, s, 2);
            if (t4 == 0) sasum[warp * 64 + mi * 16 + g + 8 * h] = s;
        }
    __syncthreads();
    if (t < 64) {
        float s = sasum[t] + sasum[64 + t] + sasum[128 + t] + sasum[192 + t];
        g_asum16[(n * 16 + blockIdx.x) * K_ + t] = s;
    }
}

// ---------------------------------------------------------------------------
// K2: vlad D[k=64, c=64] = sum_p atil[k,p]*x[c,p] via bf16 mma; asum summed
// from 16 slices; rss written as per-block slice. grid (8,32), 128 thr.
// smem 32KB: AS 16K | XS 16K (256B swizzled rows).
// ---------------------------------------------------------------------------
__global__ __launch_bounds__(128) void k2_vlad(const float* __restrict__ x,
                                               const float* __restrict__ vocabs,
                                               float* __restrict__ out) {
    __shared__ __align__(16) char sm[32768];
    u32 sb = smem_u32(sm);
    const u32 AS = sb, XS = sb + 16384;
    float* srss = (float*)sm;

    int t = threadIdx.x;
    int warp = t >> 5, lane = t & 31;
    int g = lane >> 2, t4 = lane & 3;
    int jA = lane >> 3, rA = lane & 7;
    int n = blockIdx.y, c0 = blockIdx.x * 64;

    float d[4][2][4];
#pragma unroll
    for (int a = 0; a < 4; a++)
#pragma unroll
        for (int b = 0; b < 2; b++)
#pragma unroll
            for (int q = 0; q < 4; q++) d[a][b][q] = 0.0f;

    const u16* ab = g_abf + (size_t)n * K_ * P_;
    const float* xb = x + (size_t)n * C_ * P_;

    for (int ch = 0; ch < 8; ch++) {
        int p0 = ch * 128;
        __syncthreads();
#pragma unroll
        for (int i = 0; i < 32; i++) {
            int q = t + 128 * i;
            int k = q >> 6, pp = q & 63;
            int p = 2 * pp;
            u32 e = *(const u32*)(ab + (size_t)k * P_ + p0 + p);
            u32 addr = (u32)(k * 256) + ((((u32)(p >> 3)) ^ (u32)(k & 7)) << 4) + (p & 7) * 2;
            *(u32*)(sm + addr) = e;
        }
#pragma unroll
        for (int i = 0; i < 32; i++) {
            int q = t + 128 * i;
            int cr = q >> 6, pp = q & 63;
            int p = 2 * pp;
            float2 v = *(const float2*)(xb + (size_t)(c0 + cr) * P_ + p0 + p);
            __nv_bfloat162 b2 = __float22bfloat162_rn(v);
            u32 val = *reinterpret_cast<u32*>(&b2);
            u32 addr = 16384u + (u32)(cr * 256) + ((((u32)(p >> 3)) ^ (u32)(cr & 7)) << 4) + (p & 7) * 2;
            *(u32*)(sm + addr) = val;
        }
        __syncthreads();

#pragma unroll
        for (int ks = 0; ks < 8; ks++) {
            u32 Ah[4][4], Bh[4];
#pragma unroll
            for (int mi = 0; mi < 4; mi++) {
                int k = mi * 16 + ((jA & 1) << 3) + rA;
                u32 pbv = (u32)(ks * 2 + (jA >> 1));
                ldsm4(Ah[mi], AS + k * 256 + ((pbv ^ (u32)(k & 7)) << 4));
            }
            {
                int cr = warp * 16 + ((jA >> 1) << 3) + rA;
                u32 pbv = (u32)(ks * 2 + (jA & 1));
                ldsm4(Bh, XS + cr * 256 + ((pbv ^ (u32)(cr & 7)) << 4));
            }
#pragma unroll
            for (int mi = 0; mi < 4; mi++)
#pragma unroll
                for (int nh = 0; nh < 2; nh++)
                    mma16816bf(d[mi][nh], Ah[mi], &Bh[nh * 2]);
        }
    }

    __syncthreads();
#pragma unroll
    for (int mi = 0; mi < 4; mi++) {
        int k0_ = mi * 16 + g;
        float s0 = 0.0f, s1 = 0.0f;
#pragma unroll
        for (int pt = 0; pt < 16; pt++) {
            s0 += g_asum16[(n * 16 + pt) * K_ + k0_];
            s1 += g_asum16[(n * 16 + pt) * K_ + k0_ + 8];
        }
        float r0 = 0.0f, r1 = 0.0f;
#pragma unroll
        for (int nb = 0; nb < 2; nb++) {
            int c = c0 + warp * 16 + nb * 8 + 2 * t4;
            float2 v0 = *(const float2*)(vocabs + k0_ * C_ + c);
            float2 v1 = *(const float2*)(vocabs + (k0_ + 8) * C_ + c);
            float2 o0, o1;
            o0.x = fmaf(-s0, v0.x, d[mi][nb][0]);
            o0.y = fmaf(-s0, v0.y, d[mi][nb][1]);
            o1.x = fmaf(-s1, v1.x, d[mi][nb][2]);
            o1.y = fmaf(-s1, v1.y, d[mi][nb][3]);
            r0 += o0.x * o0.x + o0.y * o0.y;
            r1 += o1.x * o1.x + o1.y * o1.y;
            *(float2*)(out + ((size_t)n * K_ + k0_) * C_ + c) = o0;
            *(float2*)(out + ((size_t)n * K_ + k0_ + 8) * C_ + c) = o1;
        }
        r0 += __shfl_xor_sync(0xffffffffu, r0, 1);
        r0 += __shfl_xor_sync(0xffffffffu, r0, 2);
        r1 += __shfl_xor_sync(0xffffffffu, r1, 1);
        r1 += __shfl_xor_sync(0xffffffffu, r1, 2);
        if (t4 == 0) {
            srss[warp * 64 + k0_] = r0;
            srss[warp * 64 + k0_ + 8] = r1;
        }
    }
    __syncthreads();
    if (t < 64) {
        float s = srss[t] + srss[64 + t] + srss[128 + t] + srss[192 + t];
        g_rss8[(n * 8 + blockIdx.x) * K_ + t] = s;
    }
}

// ---------------------------------------------------------------------------
// K3: fused scale computation + streaming normalization. grid (64, 32), 128 thr.
// ---------------------------------------------------------------------------
__global__ __launch_bounds__(128) void k3_norm(float* __restrict__ out) {
    int n = blockIdx.y, k = blockIdx.x, t = threadIdx.x;
    __shared__ float srinv[64];
    __shared__ float sns[2];
    float contrib = 0.0f;
    if (t < 64) {
        float tot = 0.0f;
#pragma unroll
        for (int ct = 0; ct < 8; ct++) tot += g_rss8[(n * 8 + ct) * K_ + t];
        float rinv = 1.0f / fmaxf(sqrtf(tot), EPSF);
        srinv[t] = rinv;
        contrib = tot * rinv * rinv;
    }
    float s = contrib;
#pragma unroll
    for (int o = 16; o; o >>= 1) s += __shfl_xor_sync(0xffffffffu, s, o);
    if (t < 64 && (t & 31) == 0) sns[t >> 5] = s;
    __syncthreads();
    float sc = srinv[k] / fmaxf(sqrtf(sns[0] + sns[1]), EPSF);
    float4* row = (float4*)(out + (size_t)n * (K_ * C_) + (size_t)k * C_);
    float4 v = row[t];
    v.x *= sc; v.y *= sc; v.z *= sc; v.w *= sc;
    row[t] = v;
}

// ---------------------------------------------------------------------------
extern "C" void kernel_launch(void* const* d_in, const int* in_sizes, int n_in,
                              void* d_out, int out_size) {
    const float* x = (const float*)d_in[0];
    const float* vocabs = (const float*)d_in[1];
    if (n_in >= 2 && in_sizes[0] == K_ * C_ && in_sizes[1] == N_ * C_ * P_) {
        vocabs = (const float*)d_in[0];
        x = (const float*)d_in[1];
    }
    float* out = (float*)d_out;

    k1_assign<<<dim3(16, 32), 128>>>(x, vocabs);
    k2_vlad<<<dim3(8, 32), 128>>>(x, vocabs, out);
    k3_norm<<<dim3(64, 32), 128>>>(out);
}

// round 12
// speedup vs baseline: 1.2995x; 1.2995x over previous
#include <cuda_runtime.h>
#include <cuda_fp16.h>
#include <cuda_bf16.h>
#include <math.h>

#define N_ 32
#define C_ 512
#define P_ 1024
#define K_ 64
#define ALPHAF 100.0f
#define EPSF 1e-12f
#define MSCALE 2048.0f
#define INV_MSCALE 4.8828125e-4f

typedef unsigned int u32;
typedef unsigned short u16;

// ---------------- scratch (no init required) ---------------------------------
__device__ float g_bias[K_];
__device__ float g_asum8[N_ * 8 * K_];        // per-(n, p-tile) asum slices
__device__ float g_rss8[N_ * 8 * K_];         // per-(n, c-tile) row-sumsq slices
__device__ u16 g_abf[(size_t)N_ * K_ * P_];   // bf16 of a*invn
// pre-split, pre-swizzled w image: 8 chunks x (h plane 8KB | m plane 8KB)
__device__ __align__(16) unsigned char g_wsw[8 * 16384];

// ---------------- helpers ----------------------------------------------------
__device__ __forceinline__ u32 smem_u32(const void* p) {
    u32 a;
    asm("{ .reg .u64 t; cvta.to.shared.u64 t, %1; cvt.u32.u64 %0, t; }" : "=r"(a) : "l"(p));
    return a;
}
__device__ __forceinline__ void ldsm4(u32* r, u32 addr) {
    asm volatile("ldmatrix.sync.aligned.m8n8.x4.shared.b16 {%0,%1,%2,%3}, [%4];"
                 : "=r"(r[0]), "=r"(r[1]), "=r"(r[2]), "=r"(r[3]) : "r"(addr));
}
__device__ __forceinline__ void ldsm4t(u32* r, u32 addr) {
    asm volatile("ldmatrix.sync.aligned.m8n8.x4.trans.shared.b16 {%0,%1,%2,%3}, [%4];"
                 : "=r"(r[0]), "=r"(r[1]), "=r"(r[2]), "=r"(r[3]) : "r"(addr));
}
__device__ __forceinline__ void mma16816(float* d, const u32* a, const u32* b) {
    asm volatile(
        "mma.sync.aligned.m16n8k16.row.col.f32.f16.f16.f32 "
        "{%0,%1,%2,%3}, {%4,%5,%6,%7}, {%8,%9}, {%0,%1,%2,%3};"
        : "+f"(d[0]), "+f"(d[1]), "+f"(d[2]), "+f"(d[3])
        : "r"(a[0]), "r"(a[1]), "r"(a[2]), "r"(a[3]), "r"(b[0]), "r"(b[1]));
}
__device__ __forceinline__ void mma16816bf(float* d, const u32* a, const u32* b) {
    asm volatile(
        "mma.sync.aligned.m16n8k16.row.col.f32.bf16.bf16.f32 "
        "{%0,%1,%2,%3}, {%4,%5,%6,%7}, {%8,%9}, {%0,%1,%2,%3};"
        : "+f"(d[0]), "+f"(d[1]), "+f"(d[2]), "+f"(d[3])
        : "r"(a[0]), "r"(a[1]), "r"(a[2]), "r"(a[3]), "r"(b[0]), "r"(b[1]));
}
__device__ __forceinline__ void split2(float v, u32& hbits, u32& mbits) {
    __half h = __float2half_rn(v);
    __half m = __float2half_rn((v - __half2float(h)) * MSCALE);
    hbits = (u32)__half_as_ushort(h);
    mbits = (u32)__half_as_ushort(m);
}

// ---------------------------------------------------------------------------
// K0w: pre-split w into the swizzled smem image + bias. grid 64 (one k/block),
// 128 thr (4 c each).
// ---------------------------------------------------------------------------
__global__ __launch_bounds__(128) void k0w_prep(const float* __restrict__ vocabs) {
    int k = blockIdx.x, t = threadIdx.x;
    int c = t * 4;
    float4 v4 = *(const float4*)(vocabs + k * C_ + c);
    float ss = v4.x * v4.x + v4.y * v4.y + v4.z * v4.z + v4.w * v4.w;

    int k7 = k & 7;
#pragma unroll
    for (int half = 0; half < 2; half++) {
        float a = (half == 0) ? v4.x : v4.z;
        float b = (half == 0) ? v4.y : v4.w;
        int cc = c + half * 2;
        u32 ha, ma, hb, mb;
        split2(2.0f * ALPHAF * a, ha, ma);
        split2(2.0f * ALPHAF * b, hb, mb);
        int ch = cc >> 6, cl = cc & 63, cb = cl >> 3;
        u32 addr = (u32)(k * 128) + (((u32)cb ^ (u32)k7) << 4) + (cl & 7) * 2;
        *(u32*)(g_wsw + ch * 16384 + addr) = ha | (hb << 16);
        *(u32*)(g_wsw + ch * 16384 + 8192 + addr) = ma | (mb << 16);
    }
    // reduce ss over block -> bias
#pragma unroll
    for (int o = 16; o; o >>= 1) ss += __shfl_xor_sync(0xffffffffu, ss, o);
    __shared__ float w4[4];
    if ((t & 31) == 0) w4[t >> 5] = ss;
    __syncthreads();
    if (t == 0) g_bias[k] = -ALPHAF * sqrtf(w4[0] + w4[1] + w4[2] + w4[3]);
}

// ---------------------------------------------------------------------------
// K1: logits D[k=64, p=128] = sum_c (2a*w)[k,c]*x[c,p]. w planes copied from
// pre-swizzled image; x split on the fly; invn in-block; asum per-block slice.
// grid (8,32), 128 thr. smem 48KB: WH 8K | WM 8K | XH 16K | XM 16K.
// ---------------------------------------------------------------------------
__global__ __launch_bounds__(128) void k1_assign(const float* __restrict__ x) {
    __shared__ __align__(16) char sm[49152];
    u32 sb = smem_u32(sm);
    const u32 WH = sb, WM = sb + 8192, XH = sb + 16384, XM = sb + 32768;
    float* ssacc = (float*)sm;            // [0,128)   post-mainloop
    float* sasum = (float*)sm + 128;      // [128,384)

    int t = threadIdx.x;
    int warp = t >> 5, lane = t & 31;
    int g = lane >> 2, t4 = lane & 3;
    int jA = lane >> 3, rA = lane & 7;
    int n = blockIdx.y, p0 = blockIdx.x * 128;
    int pw = warp * 32;

    float dh[4][4][4], dl[4][4][4];
#pragma unroll
    for (int a = 0; a < 4; a++)
#pragma unroll
        for (int b = 0; b < 4; b++)
#pragma unroll
            for (int q = 0; q < 4; q++) { dh[a][b][q] = 0.0f; dl[a][b][q] = 0.0f; }

    const float* xb = x + (size_t)n * C_ * P_ + p0;
    int px = 2 * (t & 63);
    int cpar = t >> 6;
    int nbx = px >> 3;
    float ssx = 0.0f, ssy = 0.0f;

    for (int ch = 0; ch < 8; ch++) {
        int c0 = ch * 64;
        __syncthreads();
        // stage w: straight 16B copy of pre-swizzled image (both planes)
        {
            const uint4* src = (const uint4*)(g_wsw + ch * 16384);
            uint4* dst = (uint4*)sm;
#pragma unroll
            for (int i = 0; i < 8; i++) dst[t + 128 * i] = src[t + 128 * i];
        }
        // stage x from fp32, split h/m, accumulate per-p sumsq
#pragma unroll
        for (int i = 0; i < 32; i++) {
            int cc = cpar + 2 * i;
            float2 v = *(const float2*)(xb + (size_t)(c0 + cc) * P_ + px);
            ssx = fmaf(v.x, v.x, ssx);
            ssy = fmaf(v.y, v.y, ssy);
            u32 hx, mx_, hy, my_;
            split2(v.x, hx, mx_);
            split2(v.y, hy, my_);
            u32 off = (u32)(cc * 256) + (((u32)nbx ^ (u32)(cc & 7)) << 4) + (px & 7) * 2;
            *(u32*)(sm + 16384 + off) = hx | (hy << 16);
            *(u32*)(sm + 32768 + off) = mx_ | (my_ << 16);
        }
        __syncthreads();

#pragma unroll
        for (int ks = 0; ks < 4; ks++) {
            u32 Ah[4][4], Am[4][4], Bh[2][4], Bm[2][4];
#pragma unroll
            for (int mi = 0; mi < 4; mi++) {
                int k = mi * 16 + ((jA & 1) << 3) + rA;
                int cb = ks * 2 + (jA >> 1);
                u32 addr = (u32)(k * 128) + (((u32)cb ^ (u32)(k & 7)) << 4);
                ldsm4(Ah[mi], WH + addr);
                ldsm4(Am[mi], WM + addr);
            }
#pragma unroll
            for (int ni = 0; ni < 2; ni++) {
                int c = ks * 16 + ((jA & 1) << 3) + rA;
                int nb = warp * 4 + ni * 2 + (jA >> 1);
                u32 off = (u32)(c * 256) + (((u32)nb ^ (u32)(c & 7)) << 4);
                ldsm4t(Bh[ni], XH + off);
                ldsm4t(Bm[ni], XM + off);
            }
#pragma unroll
            for (int mi = 0; mi < 4; mi++)
#pragma unroll
                for (int ni = 0; ni < 2; ni++)
#pragma unroll
                    for (int nh = 0; nh < 2; nh++) {
                        mma16816(dh[mi][ni * 2 + nh], Ah[mi], &Bh[ni][nh * 2]);
                        mma16816(dl[mi][ni * 2 + nh], Ah[mi], &Bm[ni][nh * 2]);
                        mma16816(dl[mi][ni * 2 + nh], Am[mi], &Bh[ni][nh * 2]);
                    }
        }
    }

    // ---- post-mainloop reductions into reused smem ----
    __syncthreads();
    ssacc[t] = 0.0f;
    __syncthreads();
    atomicAdd(&ssacc[px], ssx);
    atomicAdd(&ssacc[px + 1], ssy);
    __syncthreads();

    float d[4][4][4];
#pragma unroll
    for (int mi = 0; mi < 4; mi++)
#pragma unroll
        for (int nj = 0; nj < 4; nj++)
#pragma unroll
            for (int q = 0; q < 4; q++)
                d[mi][nj][q] = fmaf(dl[mi][nj][q], INV_MSCALE, dh[mi][nj][q]);

    float invp[4][2], bias[4][2];
#pragma unroll
    for (int nj = 0; nj < 4; nj++) {
        int pl = pw + nj * 8 + 2 * t4;
        invp[nj][0] = 1.0f / fmaxf(sqrtf(ssacc[pl]), EPSF);
        invp[nj][1] = 1.0f / fmaxf(sqrtf(ssacc[pl + 1]), EPSF);
    }
#pragma unroll
    for (int mi = 0; mi < 4; mi++) {
        bias[mi][0] = g_bias[mi * 16 + g];
        bias[mi][1] = g_bias[mi * 16 + g + 8];
    }
    float lg[4][4][4];
    float mx[4][2];
#pragma unroll
    for (int nj = 0; nj < 4; nj++) { mx[nj][0] = -1e30f; mx[nj][1] = -1e30f; }
#pragma unroll
    for (int mi = 0; mi < 4; mi++)
#pragma unroll
        for (int nj = 0; nj < 4; nj++) {
            lg[mi][nj][0] = fmaf(d[mi][nj][0], invp[nj][0], bias[mi][0]);
            lg[mi][nj][1] = fmaf(d[mi][nj][1], invp[nj][1], bias[mi][0]);
            lg[mi][nj][2] = fmaf(d[mi][nj][2], invp[nj][0], bias[mi][1]);
            lg[mi][nj][3] = fmaf(d[mi][nj][3], invp[nj][1], bias[mi][1]);
            mx[nj][0] = fmaxf(mx[nj][0], fmaxf(lg[mi][nj][0], lg[mi][nj][2]));
            mx[nj][1] = fmaxf(mx[nj][1], fmaxf(lg[mi][nj][1], lg[mi][nj][3]));
        }
#pragma unroll
    for (int nj = 0; nj < 4; nj++)
#pragma unroll
        for (int cc = 0; cc < 2; cc++) {
            float m = mx[nj][cc];
#pragma unroll
            for (int o = 4; o <= 16; o <<= 1) m = fmaxf(m, __shfl_xor_sync(0xffffffffu, m, o));
            mx[nj][cc] = m;
        }
    float sx[4][2];
#pragma unroll
    for (int nj = 0; nj < 4; nj++) { sx[nj][0] = 0.0f; sx[nj][1] = 0.0f; }
#pragma unroll
    for (int mi = 0; mi < 4; mi++)
#pragma unroll
        for (int nj = 0; nj < 4; nj++) {
            lg[mi][nj][0] = __expf(lg[mi][nj][0] - mx[nj][0]);
            lg[mi][nj][1] = __expf(lg[mi][nj][1] - mx[nj][1]);
            lg[mi][nj][2] = __expf(lg[mi][nj][2] - mx[nj][0]);
            lg[mi][nj][3] = __expf(lg[mi][nj][3] - mx[nj][1]);
            sx[nj][0] += lg[mi][nj][0] + lg[mi][nj][2];
            sx[nj][1] += lg[mi][nj][1] + lg[mi][nj][3];
        }
#pragma unroll
    for (int nj = 0; nj < 4; nj++)
#pragma unroll
        for (int cc = 0; cc < 2; cc++) {
            float s = sx[nj][cc];
#pragma unroll
            for (int o = 4; o <= 16; o <<= 1) s += __shfl_xor_sync(0xffffffffu, s, o);
            sx[nj][cc] = 1.0f / s;
        }
    float asl[4][2];
#pragma unroll
    for (int mi = 0; mi < 4; mi++) { asl[mi][0] = 0.0f; asl[mi][1] = 0.0f; }
    u16* ab = g_abf + (size_t)n * K_ * P_;
#pragma unroll
    for (int mi = 0; mi < 4; mi++)
#pragma unroll
        for (int nj = 0; nj < 4; nj++) {
            int p = p0 + pw + nj * 8 + 2 * t4;
            int k0_ = mi * 16 + g;
            float a00 = lg[mi][nj][0] * sx[nj][0];
            float a01 = lg[mi][nj][1] * sx[nj][1];
            float a10 = lg[mi][nj][2] * sx[nj][0];
            float a11 = lg[mi][nj][3] * sx[nj][1];
            asl[mi][0] += a00 + a01;
            asl[mi][1] += a10 + a11;
            u32 w0 = (u32)__bfloat16_as_ushort(__float2bfloat16(a00 * invp[nj][0])) |
                     ((u32)__bfloat16_as_ushort(__float2bfloat16(a01 * invp[nj][1])) << 16);
            u32 w1 = (u32)__bfloat16_as_ushort(__float2bfloat16(a10 * invp[nj][0])) |
                     ((u32)__bfloat16_as_ushort(__float2bfloat16(a11 * invp[nj][1])) << 16);
            *(u32*)(ab + (size_t)k0_ * P_ + p) = w0;
            *(u32*)(ab + (size_t)(k0_ + 8) * P_ + p) = w1;
        }
#pragma unroll
    for (int mi = 0; mi < 4; mi++)
#pragma unroll
        for (int h = 0; h < 2; h++) {
            float s = asl[mi][h];
            s += __shfl_xor_sync(0xffffffffu, s, 1);
            s += __shfl_xor_sync(0xffffffffu, s, 2);
            if (t4 == 0) sasum[warp * 64 + mi * 16 + g + 8 * h] = s;
        }
    __syncthreads();
    if (t < 64) {
        float s = sasum[t] + sasum[64 + t] + sasum[128 + t] + sasum[192 + t];
        g_asum8[(n * 8 + blockIdx.x) * K_ + t] = s;
    }
}

// ---------------------------------------------------------------------------
// K2: vlad D[k=64, c=64] = sum_p atil[k,p]*x[c,p] via bf16 mma; asum summed
// from 8 slices; rss written as per-block slice. grid (8,32), 128 thr.
// smem 32KB: AS 16K | XS 16K (256B swizzled rows).
// ---------------------------------------------------------------------------
__global__ __launch_bounds__(128) void k2_vlad(const float* __restrict__ x,
                                               const float* __restrict__ vocabs,
                                               float* __restrict__ out) {
    __shared__ __align__(16) char sm[32768];
    u32 sb = smem_u32(sm);
    const u32 AS = sb, XS = sb + 16384;
    float* srss = (float*)sm;

    int t = threadIdx.x;
    int warp = t >> 5, lane = t & 31;
    int g = lane >> 2, t4 = lane & 3;
    int jA = lane >> 3, rA = lane & 7;
    int n = blockIdx.y, c0 = blockIdx.x * 64;

    float d[4][2][4];
#pragma unroll
    for (int a = 0; a < 4; a++)
#pragma unroll
        for (int b = 0; b < 2; b++)
#pragma unroll
            for (int q = 0; q < 4; q++) d[a][b][q] = 0.0f;

    const u16* ab = g_abf + (size_t)n * K_ * P_;
    const float* xb = x + (size_t)n * C_ * P_;

    for (int ch = 0; ch < 8; ch++) {
        int p0 = ch * 128;
        __syncthreads();
#pragma unroll
        for (int i = 0; i < 32; i++) {
            int q = t + 128 * i;
            int k = q >> 6, pp = q & 63;
            int p = 2 * pp;
            u32 e = *(const u32*)(ab + (size_t)k * P_ + p0 + p);
            u32 addr = (u32)(k * 256) + ((((u32)(p >> 3)) ^ (u32)(k & 7)) << 4) + (p & 7) * 2;
            *(u32*)(sm + addr) = e;
        }
#pragma unroll
        for (int i = 0; i < 32; i++) {
            int q = t + 128 * i;
            int cr = q >> 6, pp = q & 63;
            int p = 2 * pp;
            float2 v = *(const float2*)(xb + (size_t)(c0 + cr) * P_ + p0 + p);
            __nv_bfloat162 b2 = __float22bfloat162_rn(v);
            u32 val = *reinterpret_cast<u32*>(&b2);
            u32 addr = 16384u + (u32)(cr * 256) + ((((u32)(p >> 3)) ^ (u32)(cr & 7)) << 4) + (p & 7) * 2;
            *(u32*)(sm + addr) = val;
        }
        __syncthreads();

#pragma unroll
        for (int ks = 0; ks < 8; ks++) {
            u32 Ah[4][4], Bh[4];
#pragma unroll
            for (int mi = 0; mi < 4; mi++) {
                int k = mi * 16 + ((jA & 1) << 3) + rA;
                u32 pbv = (u32)(ks * 2 + (jA >> 1));
                ldsm4(Ah[mi], AS + k * 256 + ((pbv ^ (u32)(k & 7)) << 4));
            }
            {
                int cr = warp * 16 + ((jA >> 1) << 3) + rA;
                u32 pbv = (u32)(ks * 2 + (jA & 1));
                ldsm4(Bh, XS + cr * 256 + ((pbv ^ (u32)(cr & 7)) << 4));
            }
#pragma unroll
            for (int mi = 0; mi < 4; mi++)
#pragma unroll
                for (int nh = 0; nh < 2; nh++)
                    mma16816bf(d[mi][nh], Ah[mi], &Bh[nh * 2]);
        }
    }

    __syncthreads();
#pragma unroll
    for (int mi = 0; mi < 4; mi++) {
        int k0_ = mi * 16 + g;
        float s0 = 0.0f, s1 = 0.0f;
#pragma unroll
        for (int pt = 0; pt < 8; pt++) {
            s0 += g_asum8[(n * 8 + pt) * K_ + k0_];
            s1 += g_asum8[(n * 8 + pt) * K_ + k0_ + 8];
        }
        float r0 = 0.0f, r1 = 0.0f;
#pragma unroll
        for (int nb = 0; nb < 2; nb++) {
            int c = c0 + warp * 16 + nb * 8 + 2 * t4;
            float2 v0 = *(const float2*)(vocabs + k0_ * C_ + c);
            float2 v1 = *(const float2*)(vocabs + (k0_ + 8) * C_ + c);
            float2 o0, o1;
            o0.x = fmaf(-s0, v0.x, d[mi][nb][0]);
            o0.y = fmaf(-s0, v0.y, d[mi][nb][1]);
            o1.x = fmaf(-s1, v1.x, d[mi][nb][2]);
            o1.y = fmaf(-s1, v1.y, d[mi][nb][3]);
            r0 += o0.x * o0.x + o0.y * o0.y;
            r1 += o1.x * o1.x + o1.y * o1.y;
            *(float2*)(out + ((size_t)n * K_ + k0_) * C_ + c) = o0;
            *(float2*)(out + ((size_t)n * K_ + k0_ + 8) * C_ + c) = o1;
        }
        r0 += __shfl_xor_sync(0xffffffffu, r0, 1);
        r0 += __shfl_xor_sync(0xffffffffu, r0, 2);
        r1 += __shfl_xor_sync(0xffffffffu, r1, 1);
        r1 += __shfl_xor_sync(0xffffffffu, r1, 2);
        if (t4 == 0) {
            srss[warp * 64 + k0_] = r0;
            srss[warp * 64 + k0_ + 8] = r1;
        }
    }
    __syncthreads();
    if (t < 64) {
        float s = srss[t] + srss[64 + t] + srss[128 + t] + srss[192 + t];
        g_rss8[(n * 8 + blockIdx.x) * K_ + t] = s;
    }
}

// ---------------------------------------------------------------------------
// K3: fused scale computation + streaming normalization. grid (64, 32), 128 thr.
// ---------------------------------------------------------------------------
__global__ __launch_bounds__(128) void k3_norm(float* __restrict__ out) {
    int n = blockIdx.y, k = blockIdx.x, t = threadIdx.x;
    __shared__ float srinv[64];
    __shared__ float sns[2];
    float contrib = 0.0f;
    if (t < 64) {
        float tot = 0.0f;
#pragma unroll
        for (int ct = 0; ct < 8; ct++) tot += g_rss8[(n * 8 + ct) * K_ + t];
        float rinv = 1.0f / fmaxf(sqrtf(tot), EPSF);
        srinv[t] = rinv;
        contrib = tot * rinv * rinv;
    }
    float s = contrib;
#pragma unroll
    for (int o = 16; o; o >>= 1) s += __shfl_xor_sync(0xffffffffu, s, o);
    if (t < 64 && (t & 31) == 0) sns[t >> 5] = s;
    __syncthreads();
    float sc = srinv[k] / fmaxf(sqrtf(sns[0] + sns[1]), EPSF);
    float4* row = (float4*)(out + (size_t)n * (K_ * C_) + (size_t)k * C_);
    float4 v = row[t];
    v.x *= sc; v.y *= sc; v.z *= sc; v.w *= sc;
    row[t] = v;
}

// ---------------------------------------------------------------------------
extern "C" void kernel_launch(void* const* d_in, const int* in_sizes, int n_in,
                              void* d_out, int out_size) {
    const float* x = (const float*)d_in[0];
    const float* vocabs = (const float*)d_in[1];
    if (n_in >= 2 && in_sizes[0] == K_ * C_ && in_sizes[1] == N_ * C_ * P_) {
        vocabs = (const float*)d_in[0];
        x = (const float*)d_in[1];
    }
    float* out = (float*)d_out;

    k0w_prep<<<64, 128>>>(vocabs);
    k1_assign<<<dim3(8, 32), 128>>>(x);
    k2_vlad<<<dim3(8, 32), 128>>>(x, vocabs, out);
    k3_norm<<<dim3(64, 32), 128>>>(out);
}

// round 13
// speedup vs baseline: 1.3614x; 1.0476x over previous
#include <cuda_runtime.h>
#include <cuda_fp16.h>
#include <cuda_bf16.h>
#include <math.h>

#define N_ 32
#define C_ 512
#define P_ 1024
#define K_ 64
#define ALPHAF 100.0f
#define EPSF 1e-12f
#define MSCALE 2048.0f
#define INV_MSCALE 4.8828125e-4f

typedef unsigned int u32;
typedef unsigned short u16;

// ---------------- scratch (no init required) ---------------------------------
__device__ float g_bias[K_];
__device__ float g_asum8[N_ * 8 * K_];        // per-(n, p-tile) asum slices
__device__ float g_rss8[N_ * 8 * K_];         // per-(n, c-tile) row-sumsq slices
__device__ u16 g_abf[(size_t)N_ * K_ * P_];   // bf16 of a*invn
// pre-split, pre-swizzled w image: 8 chunks x (h plane 8KB | m plane 8KB)
__device__ __align__(16) unsigned char g_wsw[8 * 16384];

// ---------------- helpers ----------------------------------------------------
__device__ __forceinline__ u32 smem_u32(const void* p) {
    u32 a;
    asm("{ .reg .u64 t; cvta.to.shared.u64 t, %1; cvt.u32.u64 %0, t; }" : "=r"(a) : "l"(p));
    return a;
}
__device__ __forceinline__ void ldsm4(u32* r, u32 addr) {
    asm volatile("ldmatrix.sync.aligned.m8n8.x4.shared.b16 {%0,%1,%2,%3}, [%4];"
                 : "=r"(r[0]), "=r"(r[1]), "=r"(r[2]), "=r"(r[3]) : "r"(addr));
}
__device__ __forceinline__ void ldsm4t(u32* r, u32 addr) {
    asm volatile("ldmatrix.sync.aligned.m8n8.x4.trans.shared.b16 {%0,%1,%2,%3}, [%4];"
                 : "=r"(r[0]), "=r"(r[1]), "=r"(r[2]), "=r"(r[3]) : "r"(addr));
}
__device__ __forceinline__ void mma16816(float* d, const u32* a, const u32* b) {
    asm volatile(
        "mma.sync.aligned.m16n8k16.row.col.f32.f16.f16.f32 "
        "{%0,%1,%2,%3}, {%4,%5,%6,%7}, {%8,%9}, {%0,%1,%2,%3};"
        : "+f"(d[0]), "+f"(d[1]), "+f"(d[2]), "+f"(d[3])
        : "r"(a[0]), "r"(a[1]), "r"(a[2]), "r"(a[3]), "r"(b[0]), "r"(b[1]));
}
__device__ __forceinline__ void mma16816bf(float* d, const u32* a, const u32* b) {
    asm volatile(
        "mma.sync.aligned.m16n8k16.row.col.f32.bf16.bf16.f32 "
        "{%0,%1,%2,%3}, {%4,%5,%6,%7}, {%8,%9}, {%0,%1,%2,%3};"
        : "+f"(d[0]), "+f"(d[1]), "+f"(d[2]), "+f"(d[3])
        : "r"(a[0]), "r"(a[1]), "r"(a[2]), "r"(a[3]), "r"(b[0]), "r"(b[1]));
}
__device__ __forceinline__ void split2(float v, u32& hbits, u32& mbits) {
    __half h = __float2half_rn(v);
    __half m = __float2half_rn((v - __half2float(h)) * MSCALE);
    hbits = (u32)__half_as_ushort(h);
    mbits = (u32)__half_as_ushort(m);
}

// ---------------------------------------------------------------------------
// K0w: pre-split w into the swizzled smem image + bias. grid 64, 128 thr.
// ---------------------------------------------------------------------------
__global__ __launch_bounds__(128) void k0w_prep(const float* __restrict__ vocabs) {
    int k = blockIdx.x, t = threadIdx.x;
    int c = t * 4;
    float4 v4 = *(const float4*)(vocabs + k * C_ + c);
    float ss = v4.x * v4.x + v4.y * v4.y + v4.z * v4.z + v4.w * v4.w;

    int k7 = k & 7;
#pragma unroll
    for (int half = 0; half < 2; half++) {
        float a = (half == 0) ? v4.x : v4.z;
        float b = (half == 0) ? v4.y : v4.w;
        int cc = c + half * 2;
        u32 ha, ma, hb, mb;
        split2(2.0f * ALPHAF * a, ha, ma);
        split2(2.0f * ALPHAF * b, hb, mb);
        int ch = cc >> 6, cl = cc & 63, cb = cl >> 3;
        u32 addr = (u32)(k * 128) + (((u32)cb ^ (u32)k7) << 4) + (cl & 7) * 2;
        *(u32*)(g_wsw + ch * 16384 + addr) = ha | (hb << 16);
        *(u32*)(g_wsw + ch * 16384 + 8192 + addr) = ma | (mb << 16);
    }
#pragma unroll
    for (int o = 16; o; o >>= 1) ss += __shfl_xor_sync(0xffffffffu, ss, o);
    __shared__ float w4[4];
    if ((t & 31) == 0) w4[t >> 5] = ss;
    __syncthreads();
    if (t == 0) g_bias[k] = -ALPHAF * sqrtf(w4[0] + w4[1] + w4[2] + w4[3]);
}

// ---------------------------------------------------------------------------
// K1: logits D[k=64, p=128] = sum_c (2a*w)[k,c]*x[c,p]. 256 threads (8 warps),
// each warp owns 64k x 16p. w copied from pre-swizzled image; x split on the
// fly; invn in-block; asum per-block slice. grid (8,32).
// smem 48KB: WH 8K | WM 8K | XH 16K | XM 16K.
// ---------------------------------------------------------------------------
__global__ __launch_bounds__(256, 2) void k1_assign(const float* __restrict__ x) {
    __shared__ __align__(16) char sm[49152];
    u32 sb = smem_u32(sm);
    const u32 WH = sb, WM = sb + 8192, XH = sb + 16384, XM = sb + 32768;
    float* ssacc = (float*)sm;            // [0,128)   post-mainloop
    float* sasum = (float*)sm + 128;      // [128,640)

    int t = threadIdx.x;
    int warp = t >> 5, lane = t & 31;
    int g = lane >> 2, t4 = lane & 3;
    int jA = lane >> 3, rA = lane & 7;
    int n = blockIdx.y, p0 = blockIdx.x * 128;
    int pw = warp * 16;

    float dh[4][2][4], dl[4][2][4];
#pragma unroll
    for (int a = 0; a < 4; a++)
#pragma unroll
        for (int b = 0; b < 2; b++)
#pragma unroll
            for (int q = 0; q < 4; q++) { dh[a][b][q] = 0.0f; dl[a][b][q] = 0.0f; }

    const float* xb = x + (size_t)n * C_ * P_ + p0;
    int px = 2 * (t & 63);      // p-pair this thread stages
    int cpar = t >> 6;          // c parity 0..3
    int nbx = px >> 3;
    float ssx = 0.0f, ssy = 0.0f;

    for (int ch = 0; ch < 8; ch++) {
        int c0 = ch * 64;
        __syncthreads();
        // stage w: straight 16B copy of pre-swizzled image (both planes)
        {
            const uint4* src = (const uint4*)(g_wsw + ch * 16384);
            uint4* dst = (uint4*)sm;
#pragma unroll
            for (int i = 0; i < 4; i++) dst[t + 256 * i] = src[t + 256 * i];
        }
        // stage x from fp32, split h/m, accumulate per-p sumsq
#pragma unroll
        for (int i = 0; i < 16; i++) {
            int cc = cpar + 4 * i;
            float2 v = *(const float2*)(xb + (size_t)(c0 + cc) * P_ + px);
            ssx = fmaf(v.x, v.x, ssx);
            ssy = fmaf(v.y, v.y, ssy);
            u32 hx, mx_, hy, my_;
            split2(v.x, hx, mx_);
            split2(v.y, hy, my_);
            u32 off = (u32)(cc * 256) + (((u32)nbx ^ (u32)(cc & 7)) << 4) + (px & 7) * 2;
            *(u32*)(sm + 16384 + off) = hx | (hy << 16);
            *(u32*)(sm + 32768 + off) = mx_ | (my_ << 16);
        }
        __syncthreads();

#pragma unroll
        for (int ks = 0; ks < 4; ks++) {
            u32 Ah[4][4], Am[4][4], Bh[4], Bm[4];
#pragma unroll
            for (int mi = 0; mi < 4; mi++) {
                int k = mi * 16 + ((jA & 1) << 3) + rA;
                int cb = ks * 2 + (jA >> 1);
                u32 addr = (u32)(k * 128) + (((u32)cb ^ (u32)(k & 7)) << 4);
                ldsm4(Ah[mi], WH + addr);
                ldsm4(Am[mi], WM + addr);
            }
            {
                int c = ks * 16 + ((jA & 1) << 3) + rA;
                int nb = warp * 2 + (jA >> 1);
                u32 off = (u32)(c * 256) + (((u32)nb ^ (u32)(c & 7)) << 4);
                ldsm4t(Bh, XH + off);
                ldsm4t(Bm, XM + off);
            }
#pragma unroll
            for (int mi = 0; mi < 4; mi++)
#pragma unroll
                for (int nh = 0; nh < 2; nh++) {
                    mma16816(dh[mi][nh], Ah[mi], &Bh[nh * 2]);
                    mma16816(dl[mi][nh], Ah[mi], &Bm[nh * 2]);
                    mma16816(dl[mi][nh], Am[mi], &Bh[nh * 2]);
                }
        }
    }

    // ---- post-mainloop reductions into reused smem ----
    __syncthreads();
    if (t < 128) ssacc[t] = 0.0f;
    __syncthreads();
    atomicAdd(&ssacc[px], ssx);
    atomicAdd(&ssacc[px + 1], ssy);
    __syncthreads();

    float d[4][2][4];
#pragma unroll
    for (int mi = 0; mi < 4; mi++)
#pragma unroll
        for (int nj = 0; nj < 2; nj++)
#pragma unroll
            for (int q = 0; q < 4; q++)
                d[mi][nj][q] = fmaf(dl[mi][nj][q], INV_MSCALE, dh[mi][nj][q]);

    float invp[2][2], bias[4][2];
#pragma unroll
    for (int nj = 0; nj < 2; nj++) {
        int pl = pw + nj * 8 + 2 * t4;
        invp[nj][0] = 1.0f / fmaxf(sqrtf(ssacc[pl]), EPSF);
        invp[nj][1] = 1.0f / fmaxf(sqrtf(ssacc[pl + 1]), EPSF);
    }
#pragma unroll
    for (int mi = 0; mi < 4; mi++) {
        bias[mi][0] = g_bias[mi * 16 + g];
        bias[mi][1] = g_bias[mi * 16 + g + 8];
    }
    float lg[4][2][4];
    float mx[2][2];
#pragma unroll
    for (int nj = 0; nj < 2; nj++) { mx[nj][0] = -1e30f; mx[nj][1] = -1e30f; }
#pragma unroll
    for (int mi = 0; mi < 4; mi++)
#pragma unroll
        for (int nj = 0; nj < 2; nj++) {
            lg[mi][nj][0] = fmaf(d[mi][nj][0], invp[nj][0], bias[mi][0]);
            lg[mi][nj][1] = fmaf(d[mi][nj][1], invp[nj][1], bias[mi][0]);
            lg[mi][nj][2] = fmaf(d[mi][nj][2], invp[nj][0], bias[mi][1]);
            lg[mi][nj][3] = fmaf(d[mi][nj][3], invp[nj][1], bias[mi][1]);
            mx[nj][0] = fmaxf(mx[nj][0], fmaxf(lg[mi][nj][0], lg[mi][nj][2]));
            mx[nj][1] = fmaxf(mx[nj][1], fmaxf(lg[mi][nj][1], lg[mi][nj][3]));
        }
#pragma unroll
    for (int nj = 0; nj < 2; nj++)
#pragma unroll
        for (int cc = 0; cc < 2; cc++) {
            float m = mx[nj][cc];
#pragma unroll
            for (int o = 4; o <= 16; o <<= 1) m = fmaxf(m, __shfl_xor_sync(0xffffffffu, m, o));
            mx[nj][cc] = m;
        }
    float sx[2][2];
#pragma unroll
    for (int nj = 0; nj < 2; nj++) { sx[nj][0] = 0.0f; sx[nj][1] = 0.0f; }
#pragma unroll
    for (int mi = 0; mi < 4; mi++)
#pragma unroll
        for (int nj = 0; nj < 2; nj++) {
            lg[mi][nj][0] = __expf(lg[mi][nj][0] - mx[nj][0]);
            lg[mi][nj][1] = __expf(lg[mi][nj][1] - mx[nj][1]);
            lg[mi][nj][2] = __expf(lg[mi][nj][2] - mx[nj][0]);
            lg[mi][nj][3] = __expf(lg[mi][nj][3] - mx[nj][1]);
            sx[nj][0] += lg[mi][nj][0] + lg[mi][nj][2];
            sx[nj][1] += lg[mi][nj][1] + lg[mi][nj][3];
        }
#pragma unroll
    for (int nj = 0; nj < 2; nj++)
#pragma unroll
        for (int cc = 0; cc < 2; cc++) {
            float s = sx[nj][cc];
#pragma unroll
            for (int o = 4; o <= 16; o <<= 1) s += __shfl_xor_sync(0xffffffffu, s, o);
            sx[nj][cc] = 1.0f / s;
        }
    float asl[4][2];
#pragma unroll
    for (int mi = 0; mi < 4; mi++) { asl[mi][0] = 0.0f; asl[mi][1] = 0.0f; }
    u16* ab = g_abf + (size_t)n * K_ * P_;
#pragma unroll
    for (int mi = 0; mi < 4; mi++)
#pragma unroll
        for (int nj = 0; nj < 2; nj++) {
            int p = p0 + pw + nj * 8 + 2 * t4;
            int k0_ = mi * 16 + g;
            float a00 = lg[mi][nj][0] * sx[nj][0];
            float a01 = lg[mi][nj][1] * sx[nj][1];
            float a10 = lg[mi][nj][2] * sx[nj][0];
            float a11 = lg[mi][nj][3] * sx[nj][1];
            asl[mi][0] += a00 + a01;
            asl[mi][1] += a10 + a11;
            u32 w0 = (u32)__bfloat16_as_ushort(__float2bfloat16(a00 * invp[nj][0])) |
                     ((u32)__bfloat16_as_ushort(__float2bfloat16(a01 * invp[nj][1])) << 16);
            u32 w1 = (u32)__bfloat16_as_ushort(__float2bfloat16(a10 * invp[nj][0])) |
                     ((u32)__bfloat16_as_ushort(__float2bfloat16(a11 * invp[nj][1])) << 16);
            *(u32*)(ab + (size_t)k0_ * P_ + p) = w0;
            *(u32*)(ab + (size_t)(k0_ + 8) * P_ + p) = w1;
        }
#pragma unroll
    for (int mi = 0; mi < 4; mi++)
#pragma unroll
        for (int h = 0; h < 2; h++) {
            float s = asl[mi][h];
            s += __shfl_xor_sync(0xffffffffu, s, 1);
            s += __shfl_xor_sync(0xffffffffu, s, 2);
            if (t4 == 0) sasum[warp * 64 + mi * 16 + g + 8 * h] = s;
        }
    __syncthreads();
    if (t < 64) {
        float s = 0.0f;
#pragma unroll
        for (int w2 = 0; w2 < 8; w2++) s += sasum[w2 * 64 + t];
        g_asum8[(n * 8 + blockIdx.x) * K_ + t] = s;
    }
}

// ---------------------------------------------------------------------------
// K2: vlad D[k=64, c=64] = sum_p atil[k,p]*x[c,p] via bf16 mma; asum summed
// from 8 slices; rss written as per-block slice. grid (8,32), 128 thr.
// smem 32KB: AS 16K | XS 16K (256B swizzled rows).
// ---------------------------------------------------------------------------
__global__ __launch_bounds__(128) void k2_vlad(const float* __restrict__ x,
                                               const float* __restrict__ vocabs,
                                               float* __restrict__ out) {
    __shared__ __align__(16) char sm[32768];
    u32 sb = smem_u32(sm);
    const u32 AS = sb, XS = sb + 16384;
    float* srss = (float*)sm;

    int t = threadIdx.x;
    int warp = t >> 5, lane = t & 31;
    int g = lane >> 2, t4 = lane & 3;
    int jA = lane >> 3, rA = lane & 7;
    int n = blockIdx.y, c0 = blockIdx.x * 64;

    float d[4][2][4];
#pragma unroll
    for (int a = 0; a < 4; a++)
#pragma unroll
        for (int b = 0; b < 2; b++)
#pragma unroll
            for (int q = 0; q < 4; q++) d[a][b][q] = 0.0f;

    const u16* ab = g_abf + (size_t)n * K_ * P_;
    const float* xb = x + (size_t)n * C_ * P_;

    for (int ch = 0; ch < 8; ch++) {
        int p0 = ch * 128;
        __syncthreads();
#pragma unroll
        for (int i = 0; i < 32; i++) {
            int q = t + 128 * i;
            int k = q >> 6, pp = q & 63;
            int p = 2 * pp;
            u32 e = *(const u32*)(ab + (size_t)k * P_ + p0 + p);
            u32 addr = (u32)(k * 256) + ((((u32)(p >> 3)) ^ (u32)(k & 7)) << 4) + (p & 7) * 2;
            *(u32*)(sm + addr) = e;
        }
#pragma unroll
        for (int i = 0; i < 32; i++) {
            int q = t + 128 * i;
            int cr = q >> 6, pp = q & 63;
            int p = 2 * pp;
            float2 v = *(const float2*)(xb + (size_t)(c0 + cr) * P_ + p0 + p);
            __nv_bfloat162 b2 = __float22bfloat162_rn(v);
            u32 val = *reinterpret_cast<u32*>(&b2);
            u32 addr = 16384u + (u32)(cr * 256) + ((((u32)(p >> 3)) ^ (u32)(cr & 7)) << 4) + (p & 7) * 2;
            *(u32*)(sm + addr) = val;
        }
        __syncthreads();

#pragma unroll
        for (int ks = 0; ks < 8; ks++) {
            u32 Ah[4][4], Bh[4];
#pragma unroll
            for (int mi = 0; mi < 4; mi++) {
                int k = mi * 16 + ((jA & 1) << 3) + rA;
                u32 pbv = (u32)(ks * 2 + (jA >> 1));
                ldsm4(Ah[mi], AS + k * 256 + ((pbv ^ (u32)(k & 7)) << 4));
            }
            {
                int cr = warp * 16 + ((jA >> 1) << 3) + rA;
                u32 pbv = (u32)(ks * 2 + (jA & 1));
                ldsm4(Bh, XS + cr * 256 + ((pbv ^ (u32)(cr & 7)) << 4));
            }
#pragma unroll
            for (int mi = 0; mi < 4; mi++)
#pragma unroll
                for (int nh = 0; nh < 2; nh++)
                    mma16816bf(d[mi][nh], Ah[mi], &Bh[nh * 2]);
        }
    }

    __syncthreads();
#pragma unroll
    for (int mi = 0; mi < 4; mi++) {
        int k0_ = mi * 16 + g;
        float s0 = 0.0f, s1 = 0.0f;
#pragma unroll
        for (int pt = 0; pt < 8; pt++) {
            s0 += g_asum8[(n * 8 + pt) * K_ + k0_];
            s1 += g_asum8[(n * 8 + pt) * K_ + k0_ + 8];
        }
        float r0 = 0.0f, r1 = 0.0f;
#pragma unroll
        for (int nb = 0; nb < 2; nb++) {
            int c = c0 + warp * 16 + nb * 8 + 2 * t4;
            float2 v0 = *(const float2*)(vocabs + k0_ * C_ + c);
            float2 v1 = *(const float2*)(vocabs + (k0_ + 8) * C_ + c);
            float2 o0, o1;
            o0.x = fmaf(-s0, v0.x, d[mi][nb][0]);
            o0.y = fmaf(-s0, v0.y, d[mi][nb][1]);
            o1.x = fmaf(-s1, v1.x, d[mi][nb][2]);
            o1.y = fmaf(-s1, v1.y, d[mi][nb][3]);
            r0 += o0.x * o0.x + o0.y * o0.y;
            r1 += o1.x * o1.x + o1.y * o1.y;
            *(float2*)(out + ((size_t)n * K_ + k0_) * C_ + c) = o0;
            *(float2*)(out + ((size_t)n * K_ + k0_ + 8) * C_ + c) = o1;
        }
        r0 += __shfl_xor_sync(0xffffffffu, r0, 1);
        r0 += __shfl_xor_sync(0xffffffffu, r0, 2);
        r1 += __shfl_xor_sync(0xffffffffu, r1, 1);
        r1 += __shfl_xor_sync(0xffffffffu, r1, 2);
        if (t4 == 0) {
            srss[warp * 64 + k0_] = r0;
            srss[warp * 64 + k0_ + 8] = r1;
        }
    }
    __syncthreads();
    if (t < 64) {
        float s = srss[t] + srss[64 + t] + srss[128 + t] + srss[192 + t];
        g_rss8[(n * 8 + blockIdx.x) * K_ + t] = s;
    }
}

// ---------------------------------------------------------------------------
// K3: fused scale computation + streaming normalization. grid (64, 32), 128 thr.
// ---------------------------------------------------------------------------
__global__ __launch_bounds__(128) void k3_norm(float* __restrict__ out) {
    int n = blockIdx.y, k = blockIdx.x, t = threadIdx.x;
    __shared__ float srinv[64];
    __shared__ float sns[2];
    float contrib = 0.0f;
    if (t < 64) {
        float tot = 0.0f;
#pragma unroll
        for (int ct = 0; ct < 8; ct++) tot += g_rss8[(n * 8 + ct) * K_ + t];
        float rinv = 1.0f / fmaxf(sqrtf(tot), EPSF);
        srinv[t] = rinv;
        contrib = tot * rinv * rinv;
    }
    float s = contrib;
#pragma unroll
    for (int o = 16; o; o >>= 1) s += __shfl_xor_sync(0xffffffffu, s, o);
    if (t < 64 && (t & 31) == 0) sns[t >> 5] = s;
    __syncthreads();
    float sc = srinv[k] / fmaxf(sqrtf(sns[0] + sns[1]), EPSF);
    float4* row = (float4*)(out + (size_t)n * (K_ * C_) + (size_t)k * C_);
    float4 v = row[t];
    v.x *= sc; v.y *= sc; v.z *= sc; v.w *= sc;
    row[t] = v;
}

// ---------------------------------------------------------------------------
extern "C" void kernel_launch(void* const* d_in, const int* in_sizes, int n_in,
                              void* d_out, int out_size) {
    const float* x = (const float*)d_in[0];
    const float* vocabs = (const float*)d_in[1];
    if (n_in >= 2 && in_sizes[0] == K_ * C_ && in_sizes[1] == N_ * C_ * P_) {
        vocabs = (const float*)d_in[0];
        x = (const float*)d_in[1];
    }
    float* out = (float*)d_out;

    k0w_prep<<<64, 128>>>(vocabs);
    k1_assign<<<dim3(8, 32), 256>>>(x);
    k2_vlad<<<dim3(8, 32), 128>>>(x, vocabs, out);
    k3_norm<<<dim3(64, 32), 128>>>(out);
}

// round 14
// speedup vs baseline: 1.3622x; 1.0006x over previous
#include <cuda_runtime.h>
#include <cuda_fp16.h>
#include <cuda_bf16.h>
#include <math.h>

#define N_ 32
#define C_ 512
#define P_ 1024
#define K_ 64
#define ALPHAF 100.0f
#define EPSF 1e-12f
#define MSCALE 2048.0f
#define INV_MSCALE 4.8828125e-4f

typedef unsigned int u32;
typedef unsigned short u16;

// ---------------- scratch (no init required) ---------------------------------
__device__ float g_bias[K_];
__device__ float g_asum8[N_ * 8 * K_];        // per-(n, p-tile) asum slices
__device__ float g_rss8[N_ * 8 * K_];         // per-(n, c-tile) row-sumsq slices
__device__ u16 g_abf[(size_t)N_ * K_ * P_];   // bf16 of a*invn
// pre-split, pre-swizzled w image: 8 chunks x (h plane 8KB | m plane 8KB)
__device__ __align__(16) unsigned char g_wsw[8 * 16384];

// ---------------- helpers ----------------------------------------------------
__device__ __forceinline__ u32 smem_u32(const void* p) {
    u32 a;
    asm("{ .reg .u64 t; cvta.to.shared.u64 t, %1; cvt.u32.u64 %0, t; }" : "=r"(a) : "l"(p));
    return a;
}
__device__ __forceinline__ void ldsm4(u32* r, u32 addr) {
    asm volatile("ldmatrix.sync.aligned.m8n8.x4.shared.b16 {%0,%1,%2,%3}, [%4];"
                 : "=r"(r[0]), "=r"(r[1]), "=r"(r[2]), "=r"(r[3]) : "r"(addr));
}
__device__ __forceinline__ void ldsm4t(u32* r, u32 addr) {
    asm volatile("ldmatrix.sync.aligned.m8n8.x4.trans.shared.b16 {%0,%1,%2,%3}, [%4];"
                 : "=r"(r[0]), "=r"(r[1]), "=r"(r[2]), "=r"(r[3]) : "r"(addr));
}
__device__ __forceinline__ void mma16816(float* d, const u32* a, const u32* b) {
    asm volatile(
        "mma.sync.aligned.m16n8k16.row.col.f32.f16.f16.f32 "
        "{%0,%1,%2,%3}, {%4,%5,%6,%7}, {%8,%9}, {%0,%1,%2,%3};"
        : "+f"(d[0]), "+f"(d[1]), "+f"(d[2]), "+f"(d[3])
        : "r"(a[0]), "r"(a[1]), "r"(a[2]), "r"(a[3]), "r"(b[0]), "r"(b[1]));
}
__device__ __forceinline__ void mma16816bf(float* d, const u32* a, const u32* b) {
    asm volatile(
        "mma.sync.aligned.m16n8k16.row.col.f32.bf16.bf16.f32 "
        "{%0,%1,%2,%3}, {%4,%5,%6,%7}, {%8,%9}, {%0,%1,%2,%3};"
        : "+f"(d[0]), "+f"(d[1]), "+f"(d[2]), "+f"(d[3])
        : "r"(a[0]), "r"(a[1]), "r"(a[2]), "r"(a[3]), "r"(b[0]), "r"(b[1]));
}
__device__ __forceinline__ void split2(float v, u32& hbits, u32& mbits) {
    __half h = __float2half_rn(v);
    __half m = __float2half_rn((v - __half2float(h)) * MSCALE);
    hbits = (u32)__half_as_ushort(h);
    mbits = (u32)__half_as_ushort(m);
}

// ---------------------------------------------------------------------------
// K0w: pre-split w into the swizzled smem image + bias. grid 64, 128 thr.
// ---------------------------------------------------------------------------
__global__ __launch_bounds__(128) void k0w_prep(const float* __restrict__ vocabs) {
    int k = blockIdx.x, t = threadIdx.x;
    int c = t * 4;
    float4 v4 = *(const float4*)(vocabs + k * C_ + c);
    float ss = v4.x * v4.x + v4.y * v4.y + v4.z * v4.z + v4.w * v4.w;

    int k7 = k & 7;
#pragma unroll
    for (int half = 0; half < 2; half++) {
        float a = (half == 0) ? v4.x : v4.z;
        float b = (half == 0) ? v4.y : v4.w;
        int cc = c + half * 2;
        u32 ha, ma, hb, mb;
        split2(2.0f * ALPHAF * a, ha, ma);
        split2(2.0f * ALPHAF * b, hb, mb);
        int ch = cc >> 6, cl = cc & 63, cb = cl >> 3;
        u32 addr = (u32)(k * 128) + (((u32)cb ^ (u32)k7) << 4) + (cl & 7) * 2;
        *(u32*)(g_wsw + ch * 16384 + addr) = ha | (hb << 16);
        *(u32*)(g_wsw + ch * 16384 + 8192 + addr) = ma | (mb << 16);
    }
#pragma unroll
    for (int o = 16; o; o >>= 1) ss += __shfl_xor_sync(0xffffffffu, ss, o);
    __shared__ float w4[4];
    if ((t & 31) == 0) w4[t >> 5] = ss;
    __syncthreads();
    if (t == 0) g_bias[k] = -ALPHAF * sqrtf(w4[0] + w4[1] + w4[2] + w4[3]);
}

// ---------------------------------------------------------------------------
// K1: logits D[k=64, p=128] = sum_c (2a*w)[k,c]*x[c,p]. 256 threads (8 warps),
// each warp owns 64k x 16p. Double-buffered W+X smem (dynamic, 96KB) -> ONE
// barrier per chunk; staging of chunk ch overlaps laggards' MMA of ch-1.
// Layout: W0 16K | W1 16K | X0 32K | X1 32K. grid (8,32).
// ---------------------------------------------------------------------------
__global__ __launch_bounds__(256, 2) void k1_assign(const float* __restrict__ x) {
    extern __shared__ __align__(16) char sm[];
    u32 sb = smem_u32(sm);
    float* ssacc = (float*)sm;            // [0,128)   post-mainloop (W0 region)
    float* sasum = (float*)sm + 128;      // [128,640)

    int t = threadIdx.x;
    int warp = t >> 5, lane = t & 31;
    int g = lane >> 2, t4 = lane & 3;
    int jA = lane >> 3, rA = lane & 7;
    int n = blockIdx.y, p0 = blockIdx.x * 128;
    int pw = warp * 16;

    float dh[4][2][4], dl[4][2][4];
#pragma unroll
    for (int a = 0; a < 4; a++)
#pragma unroll
        for (int b = 0; b < 2; b++)
#pragma unroll
            for (int q = 0; q < 4; q++) { dh[a][b][q] = 0.0f; dl[a][b][q] = 0.0f; }

    const float* xb = x + (size_t)n * C_ * P_ + p0;
    int px = 2 * (t & 63);      // p-pair this thread stages
    int cpar = t >> 6;          // c parity 0..3
    int nbx = px >> 3;
    float ssx = 0.0f, ssy = 0.0f;

    for (int ch = 0; ch < 8; ch++) {
        int c0 = ch * 64;
        u32 wbase = (u32)((ch & 1) * 16384);
        u32 xbase = 32768u + (u32)((ch & 1) * 32768);
        // stage w: 16B copy of pre-swizzled image into this chunk's buffer
        {
            const uint4* src = (const uint4*)(g_wsw + ch * 16384);
            uint4* dst = (uint4*)(sm + wbase);
#pragma unroll
            for (int i = 0; i < 4; i++) dst[t + 256 * i] = src[t + 256 * i];
        }
        // stage x from fp32, split h/m, accumulate per-p sumsq
#pragma unroll
        for (int i = 0; i < 16; i++) {
            int cc = cpar + 4 * i;
            float2 v = *(const float2*)(xb + (size_t)(c0 + cc) * P_ + px);
            ssx = fmaf(v.x, v.x, ssx);
            ssy = fmaf(v.y, v.y, ssy);
            u32 hx, mx_, hy, my_;
            split2(v.x, hx, mx_);
            split2(v.y, hy, my_);
            u32 off = (u32)(cc * 256) + (((u32)nbx ^ (u32)(cc & 7)) << 4) + (px & 7) * 2;
            *(u32*)(sm + xbase + off) = hx | (hy << 16);
            *(u32*)(sm + xbase + 16384 + off) = mx_ | (my_ << 16);
        }
        __syncthreads();
        // MMA on this chunk's buffers (next iteration writes the OTHER buffer,
        // whose prior readers all passed this barrier -> safe without 2nd sync)
        u32 WHb = sb + wbase, WMb = sb + wbase + 8192;
        u32 XHb = sb + xbase, XMb = sb + xbase + 16384;
#pragma unroll
        for (int ks = 0; ks < 4; ks++) {
            u32 Ah[4][4], Am[4][4], Bh[4], Bm[4];
#pragma unroll
            for (int mi = 0; mi < 4; mi++) {
                int k = mi * 16 + ((jA & 1) << 3) + rA;
                int cb = ks * 2 + (jA >> 1);
                u32 addr = (u32)(k * 128) + (((u32)cb ^ (u32)(k & 7)) << 4);
                ldsm4(Ah[mi], WHb + addr);
                ldsm4(Am[mi], WMb + addr);
            }
            {
                int c = ks * 16 + ((jA & 1) << 3) + rA;
                int nb = warp * 2 + (jA >> 1);
                u32 off = (u32)(c * 256) + (((u32)nb ^ (u32)(c & 7)) << 4);
                ldsm4t(Bh, XHb + off);
                ldsm4t(Bm, XMb + off);
            }
#pragma unroll
            for (int mi = 0; mi < 4; mi++)
#pragma unroll
                for (int nh = 0; nh < 2; nh++) {
                    mma16816(dh[mi][nh], Ah[mi], &Bh[nh * 2]);
                    mma16816(dl[mi][nh], Ah[mi], &Bm[nh * 2]);
                    mma16816(dl[mi][nh], Am[mi], &Bh[nh * 2]);
                }
        }
    }

    // ---- post-mainloop reductions (reuse W0 region; MMA(7) used buf 1) ----
    __syncthreads();
    if (t < 128) ssacc[t] = 0.0f;
    __syncthreads();
    atomicAdd(&ssacc[px], ssx);
    atomicAdd(&ssacc[px + 1], ssy);
    __syncthreads();

    float d[4][2][4];
#pragma unroll
    for (int mi = 0; mi < 4; mi++)
#pragma unroll
        for (int nj = 0; nj < 2; nj++)
#pragma unroll
            for (int q = 0; q < 4; q++)
                d[mi][nj][q] = fmaf(dl[mi][nj][q], INV_MSCALE, dh[mi][nj][q]);

    float invp[2][2], bias[4][2];
#pragma unroll
    for (int nj = 0; nj < 2; nj++) {
        int pl = pw + nj * 8 + 2 * t4;
        invp[nj][0] = 1.0f / fmaxf(sqrtf(ssacc[pl]), EPSF);
        invp[nj][1] = 1.0f / fmaxf(sqrtf(ssacc[pl + 1]), EPSF);
    }
#pragma unroll
    for (int mi = 0; mi < 4; mi++) {
        bias[mi][0] = g_bias[mi * 16 + g];
        bias[mi][1] = g_bias[mi * 16 + g + 8];
    }
    float lg[4][2][4];
    float mx[2][2];
#pragma unroll
    for (int nj = 0; nj < 2; nj++) { mx[nj][0] = -1e30f; mx[nj][1] = -1e30f; }
#pragma unroll
    for (int mi = 0; mi < 4; mi++)
#pragma unroll
        for (int nj = 0; nj < 2; nj++) {
            lg[mi][nj][0] = fmaf(d[mi][nj][0], invp[nj][0], bias[mi][0]);
            lg[mi][nj][1] = fmaf(d[mi][nj][1], invp[nj][1], bias[mi][0]);
            lg[mi][nj][2] = fmaf(d[mi][nj][2], invp[nj][0], bias[mi][1]);
            lg[mi][nj][3] = fmaf(d[mi][nj][3], invp[nj][1], bias[mi][1]);
            mx[nj][0] = fmaxf(mx[nj][0], fmaxf(lg[mi][nj][0], lg[mi][nj][2]));
            mx[nj][1] = fmaxf(mx[nj][1], fmaxf(lg[mi][nj][1], lg[mi][nj][3]));
        }
#pragma unroll
    for (int nj = 0; nj < 2; nj++)
#pragma unroll
        for (int cc = 0; cc < 2; cc++) {
            float m = mx[nj][cc];
#pragma unroll
            for (int o = 4; o <= 16; o <<= 1) m = fmaxf(m, __shfl_xor_sync(0xffffffffu, m, o));
            mx[nj][cc] = m;
        }
    float sx[2][2];
#pragma unroll
    for (int nj = 0; nj < 2; nj++) { sx[nj][0] = 0.0f; sx[nj][1] = 0.0f; }
#pragma unroll
    for (int mi = 0; mi < 4; mi++)
#pragma unroll
        for (int nj = 0; nj < 2; nj++) {
            lg[mi][nj][0] = __expf(lg[mi][nj][0] - mx[nj][0]);
            lg[mi][nj][1] = __expf(lg[mi][nj][1] - mx[nj][1]);
            lg[mi][nj][2] = __expf(lg[mi][nj][2] - mx[nj][0]);
            lg[mi][nj][3] = __expf(lg[mi][nj][3] - mx[nj][1]);
            sx[nj][0] += lg[mi][nj][0] + lg[mi][nj][2];
            sx[nj][1] += lg[mi][nj][1] + lg[mi][nj][3];
        }
#pragma unroll
    for (int nj = 0; nj < 2; nj++)
#pragma unroll
        for (int cc = 0; cc < 2; cc++) {
            float s = sx[nj][cc];
#pragma unroll
            for (int o = 4; o <= 16; o <<= 1) s += __shfl_xor_sync(0xffffffffu, s, o);
            sx[nj][cc] = 1.0f / s;
        }
    float asl[4][2];
#pragma unroll
    for (int mi = 0; mi < 4; mi++) { asl[mi][0] = 0.0f; asl[mi][1] = 0.0f; }
    u16* ab = g_abf + (size_t)n * K_ * P_;
#pragma unroll
    for (int mi = 0; mi < 4; mi++)
#pragma unroll
        for (int nj = 0; nj < 2; nj++) {
            int p = p0 + pw + nj * 8 + 2 * t4;
            int k0_ = mi * 16 + g;
            float a00 = lg[mi][nj][0] * sx[nj][0];
            float a01 = lg[mi][nj][1] * sx[nj][1];
            float a10 = lg[mi][nj][2] * sx[nj][0];
            float a11 = lg[mi][nj][3] * sx[nj][1];
            asl[mi][0] += a00 + a01;
            asl[mi][1] += a10 + a11;
            u32 w0 = (u32)__bfloat16_as_ushort(__float2bfloat16(a00 * invp[nj][0])) |
                     ((u32)__bfloat16_as_ushort(__float2bfloat16(a01 * invp[nj][1])) << 16);
            u32 w1 = (u32)__bfloat16_as_ushort(__float2bfloat16(a10 * invp[nj][0])) |
                     ((u32)__bfloat16_as_ushort(__float2bfloat16(a11 * invp[nj][1])) << 16);
            *(u32*)(ab + (size_t)k0_ * P_ + p) = w0;
            *(u32*)(ab + (size_t)(k0_ + 8) * P_ + p) = w1;
        }
#pragma unroll
    for (int mi = 0; mi < 4; mi++)
#pragma unroll
        for (int h = 0; h < 2; h++) {
            float s = asl[mi][h];
            s += __shfl_xor_sync(0xffffffffu, s, 1);
            s += __shfl_xor_sync(0xffffffffu, s, 2);
            if (t4 == 0) sasum[warp * 64 + mi * 16 + g + 8 * h] = s;
        }
    __syncthreads();
    if (t < 64) {
        float s = 0.0f;
#pragma unroll
        for (int w2 = 0; w2 < 8; w2++) s += sasum[w2 * 64 + t];
        g_asum8[(n * 8 + blockIdx.x) * K_ + t] = s;
    }
}

// ---------------------------------------------------------------------------
// K2: vlad D[k=64, c=64] = sum_p atil[k,p]*x[c,p] via bf16 mma; asum summed
// from 8 slices; rss written as per-block slice. grid (8,32), 128 thr.
// smem 32KB: AS 16K | XS 16K (256B swizzled rows).
// ---------------------------------------------------------------------------
__global__ __launch_bounds__(128) void k2_vlad(const float* __restrict__ x,
                                               const float* __restrict__ vocabs,
                                               float* __restrict__ out) {
    __shared__ __align__(16) char sm[32768];
    u32 sb = smem_u32(sm);
    const u32 AS = sb, XS = sb + 16384;
    float* srss = (float*)sm;

    int t = threadIdx.x;
    int warp = t >> 5, lane = t & 31;
    int g = lane >> 2, t4 = lane & 3;
    int jA = lane >> 3, rA = lane & 7;
    int n = blockIdx.y, c0 = blockIdx.x * 64;

    float d[4][2][4];
#pragma unroll
    for (int a = 0; a < 4; a++)
#pragma unroll
        for (int b = 0; b < 2; b++)
#pragma unroll
            for (int q = 0; q < 4; q++) d[a][b][q] = 0.0f;

    const u16* ab = g_abf + (size_t)n * K_ * P_;
    const float* xb = x + (size_t)n * C_ * P_;

    for (int ch = 0; ch < 8; ch++) {
        int p0 = ch * 128;
        __syncthreads();
#pragma unroll
        for (int i = 0; i < 32; i++) {
            int q = t + 128 * i;
            int k = q >> 6, pp = q & 63;
            int p = 2 * pp;
            u32 e = *(const u32*)(ab + (size_t)k * P_ + p0 + p);
            u32 addr = (u32)(k * 256) + ((((u32)(p >> 3)) ^ (u32)(k & 7)) << 4) + (p & 7) * 2;
            *(u32*)(sm + addr) = e;
        }
#pragma unroll
        for (int i = 0; i < 32; i++) {
            int q = t + 128 * i;
            int cr = q >> 6, pp = q & 63;
            int p = 2 * pp;
            float2 v = *(const float2*)(xb + (size_t)(c0 + cr) * P_ + p0 + p);
            __nv_bfloat162 b2 = __float22bfloat162_rn(v);
            u32 val = *reinterpret_cast<u32*>(&b2);
            u32 addr = 16384u + (u32)(cr * 256) + ((((u32)(p >> 3)) ^ (u32)(cr & 7)) << 4) + (p & 7) * 2;
            *(u32*)(sm + addr) = val;
        }
        __syncthreads();

#pragma unroll
        for (int ks = 0; ks < 8; ks++) {
            u32 Ah[4][4], Bh[4];
#pragma unroll
            for (int mi = 0; mi < 4; mi++) {
                int k = mi * 16 + ((jA & 1) << 3) + rA;
                u32 pbv = (u32)(ks * 2 + (jA >> 1));
                ldsm4(Ah[mi], AS + k * 256 + ((pbv ^ (u32)(k & 7)) << 4));
            }
            {
                int cr = warp * 16 + ((jA >> 1) << 3) + rA;
                u32 pbv = (u32)(ks * 2 + (jA & 1));
                ldsm4(Bh, XS + cr * 256 + ((pbv ^ (u32)(cr & 7)) << 4));
            }
#pragma unroll
            for (int mi = 0; mi < 4; mi++)
#pragma unroll
                for (int nh = 0; nh < 2; nh++)
                    mma16816bf(d[mi][nh], Ah[mi], &Bh[nh * 2]);
        }
    }

    __syncthreads();
#pragma unroll
    for (int mi = 0; mi < 4; mi++) {
        int k0_ = mi * 16 + g;
        float s0 = 0.0f, s1 = 0.0f;
#pragma unroll
        for (int pt = 0; pt < 8; pt++) {
            s0 += g_asum8[(n * 8 + pt) * K_ + k0_];
            s1 += g_asum8[(n * 8 + pt) * K_ + k0_ + 8];
        }
        float r0 = 0.0f, r1 = 0.0f;
#pragma unroll
        for (int nb = 0; nb < 2; nb++) {
            int c = c0 + warp * 16 + nb * 8 + 2 * t4;
            float2 v0 = *(const float2*)(vocabs + k0_ * C_ + c);
            float2 v1 = *(const float2*)(vocabs + (k0_ + 8) * C_ + c);
            float2 o0, o1;
            o0.x = fmaf(-s0, v0.x, d[mi][nb][0]);
            o0.y = fmaf(-s0, v0.y, d[mi][nb][1]);
            o1.x = fmaf(-s1, v1.x, d[mi][nb][2]);
            o1.y = fmaf(-s1, v1.y, d[mi][nb][3]);
            r0 += o0.x * o0.x + o0.y * o0.y;
            r1 += o1.x * o1.x + o1.y * o1.y;
            *(float2*)(out + ((size_t)n * K_ + k0_) * C_ + c) = o0;
            *(float2*)(out + ((size_t)n * K_ + k0_ + 8) * C_ + c) = o1;
        }
        r0 += __shfl_xor_sync(0xffffffffu, r0, 1);
        r0 += __shfl_xor_sync(0xffffffffu, r0, 2);
        r1 += __shfl_xor_sync(0xffffffffu, r1, 1);
        r1 += __shfl_xor_sync(0xffffffffu, r1, 2);
        if (t4 == 0) {
            srss[warp * 64 + k0_] = r0;
            srss[warp * 64 + k0_ + 8] = r1;
        }
    }
    __syncthreads();
    if (t < 64) {
        float s = srss[t] + srss[64 + t] + srss[128 + t] + srss[192 + t];
        g_rss8[(n * 8 + blockIdx.x) * K_ + t] = s;
    }
}

// ---------------------------------------------------------------------------
// K3: fused scale computation + streaming normalization. grid (64, 32), 128 thr.
// ---------------------------------------------------------------------------
__global__ __launch_bounds__(128) void k3_norm(float* __restrict__ out) {
    int n = blockIdx.y, k = blockIdx.x, t = threadIdx.x;
    __shared__ float srinv[64];
    __shared__ float sns[2];
    float contrib = 0.0f;
    if (t < 64) {
        float tot = 0.0f;
#pragma unroll
        for (int ct = 0; ct < 8; ct++) tot += g_rss8[(n * 8 + ct) * K_ + t];
        float rinv = 1.0f / fmaxf(sqrtf(tot), EPSF);
        srinv[t] = rinv;
        contrib = tot * rinv * rinv;
    }
    float s = contrib;
#pragma unroll
    for (int o = 16; o; o >>= 1) s += __shfl_xor_sync(0xffffffffu, s, o);
    if (t < 64 && (t & 31) == 0) sns[t >> 5] = s;
    __syncthreads();
    float sc = srinv[k] / fmaxf(sqrtf(sns[0] + sns[1]), EPSF);
    float4* row = (float4*)(out + (size_t)n * (K_ * C_) + (size_t)k * C_);
    float4 v = row[t];
    v.x *= sc; v.y *= sc; v.z *= sc; v.w *= sc;
    row[t] = v;
}

// ---------------------------------------------------------------------------
extern "C" void kernel_launch(void* const* d_in, const int* in_sizes, int n_in,
                              void* d_out, int out_size) {
    const float* x = (const float*)d_in[0];
    const float* vocabs = (const float*)d_in[1];
    if (n_in >= 2 && in_sizes[0] == K_ * C_ && in_sizes[1] == N_ * C_ * P_) {
        vocabs = (const float*)d_in[0];
        x = (const float*)d_in[1];
    }
    float* out = (float*)d_out;

    static int attr_done = 0;
    if (!attr_done) {
        cudaFuncSetAttribute(k1_assign, cudaFuncAttributeMaxDynamicSharedMemorySize, 98304);
        attr_done = 1;
    }

    k0w_prep<<<64, 128>>>(vocabs);
    k1_assign<<<dim3(8, 32), 256, 98304>>>(x);
    k2_vlad<<<dim3(8, 32), 128>>>(x, vocabs, out);
    k3_norm<<<dim3(64, 32), 128>>>(out);
}